// round 14
// baseline (speedup 1.0000x reference)
#include <cuda_runtime.h>
#include <cstdint>

#define EMBED   1024
#define NHEADS  16
#define HDIM    64
#define BATCH   4
#define SEQ     2048
#define MROWS   (BATCH * SEQ)                   // 8192
#define HEADEL  (BATCH * NHEADS * SEQ * HDIM)   // 8388608
#define EE      (EMBED * EMBED)

// Scratch (static device globals: allocation-free rule).
__device__ float g_Q[HEADEL];
__device__ float g_K[HEADEL];
__device__ float g_V[HEADEL];
__device__ float g_rq[MROWS * EMBED];
__device__ float g_rk[MROWS * EMBED];
__device__ float g_rv[MROWS * EMBED];
__device__ float g_rw[4 * EE];

// ---------------- helpers ----------------
__device__ __forceinline__ uint32_t f2tf(float x) {
    uint32_t u;
    asm("cvt.rna.tf32.f32 %0, %1;" : "=r"(u) : "f"(x));
    return u;
}
__device__ __forceinline__ float tf32r(float x) {
    return __uint_as_float(f2tf(x));
}
__device__ __forceinline__ float ex2(float x) {
    float y;
    asm("ex2.approx.f32 %0, %1;" : "=f"(y) : "f"(x));
    return y;
}
__device__ __forceinline__ void mma8(float* d, const uint32_t* a, const uint32_t* b) {
    asm volatile(
        "mma.sync.aligned.m16n8k8.row.col.f32.tf32.tf32.f32 "
        "{%0,%1,%2,%3},{%4,%5,%6,%7},{%8,%9},{%0,%1,%2,%3};\n"
        : "+f"(d[0]), "+f"(d[1]), "+f"(d[2]), "+f"(d[3])
        : "r"(a[0]), "r"(a[1]), "r"(a[2]), "r"(a[3]), "r"(b[0]), "r"(b[1]));
}
__device__ __forceinline__ void cp16(float* s, const float* g) {
    uint32_t sa = (uint32_t)__cvta_generic_to_shared(s);
    asm volatile("cp.async.cg.shared.global [%0], [%1], 16;" :: "r"(sa), "l"(g));
}
#define CP_COMMIT() asm volatile("cp.async.commit_group;")
#define CP_WAIT0()  asm volatile("cp.async.wait_group 0;")
#define CP_WAIT1()  asm volatile("cp.async.wait_group 1;")

__device__ __forceinline__ uint32_t smem_u32(const void* p) {
    return (uint32_t)__cvta_generic_to_shared(p);
}
// ldmatrix x4 of 8x8 b32 tiles (b16 form, no trans; dtype-agnostic 16B row moves)
__device__ __forceinline__ void ldsm_x4(uint32_t* r, uint32_t addr) {
    asm volatile("ldmatrix.sync.aligned.m8n8.x4.shared.b16 {%0,%1,%2,%3}, [%4];"
                 : "=r"(r[0]), "=r"(r[1]), "=r"(r[2]), "=r"(r[3]) : "r"(addr));
}

// ---------------- single fused pre-round to tf32 (rna), 7 tensors ------------
__global__ void round_all_kernel(const float4* __restrict__ a0, float4* __restrict__ d0,
                                 const float4* __restrict__ a1, float4* __restrict__ d1,
                                 const float4* __restrict__ a2, float4* __restrict__ d2,
                                 const float4* __restrict__ w0, const float4* __restrict__ w1,
                                 const float4* __restrict__ w2, const float4* __restrict__ w3,
                                 float4* __restrict__ wdst, int n4x, int n4w)
{
    const int y = blockIdx.y;
    const float4* src;
    float4* dst;
    int n4;
    if (y < 3) {
        src = (y == 0) ? a0 : (y == 1) ? a1 : a2;
        dst = (y == 0) ? d0 : (y == 1) ? d1 : d2;
        n4  = n4x;
    } else {
        src = (y == 3) ? w0 : (y == 4) ? w1 : (y == 5) ? w2 : w3;
        dst = wdst + (size_t)(y - 3) * (EE / 4);
        n4  = n4w;
    }
    for (int i = blockIdx.x * blockDim.x + threadIdx.x; i < n4;
         i += gridDim.x * blockDim.x) {
        float4 v = src[i];
        dst[i] = make_float4(tf32r(v.x), tf32r(v.y), tf32r(v.z), tf32r(v.w));
    }
}

// ---------------- TN GEMM body: out = X @ W^T + bias (mma.sync + ldmatrix) ---
// 3-stage cp.async, K=32 chunks, 2 CTA/SM (108 KB smem) — measured-best config.
#define GEMM_BUF 9216            // floats per buffer (sA 128*36 + sB 128*36)
#define GEMM_STAGES 3
#define GEMM_SMEM (GEMM_STAGES * GEMM_BUF * 4)

template<int MODE>
__device__ __forceinline__ void gemm_body(const float* __restrict__ X,
                                          const float* __restrict__ W,
                                          const float* __restrict__ bias,
                                          float* __restrict__ out,
                                          float* smem, int bm, int bn)
{
    constexpr int K = EMBED, N = EMBED;
    const int tid  = threadIdx.x;
    const int lane = tid & 31;
    const int wid  = tid >> 5;
    const int wm   = wid & 1;
    const int wn   = wid >> 1;
    const int r    = lane >> 2;
    const int c    = lane & 3;
    const int lrow = lane & 7;
    const int grp  = lane >> 3;

    const uint32_t aoff = ((wm * 64 + (grp & 1) * 8 + lrow) * 36 + (grp >> 1) * 4) * 4;
    const uint32_t boff = ((wn * 32 + (grp >> 1) * 8 + lrow) * 36 + (grp & 1) * 4) * 4;

    float acc[4][4][4];
    #pragma unroll
    for (int mt = 0; mt < 4; ++mt)
        #pragma unroll
        for (int nt = 0; nt < 4; ++nt)
            #pragma unroll
            for (int e = 0; e < 4; ++e) acc[mt][nt][e] = 0.f;

    #pragma unroll
    for (int pre = 0; pre < 2; ++pre) {
        float* sA = smem + pre * GEMM_BUF;
        float* sB = sA + 4608;
        int kt = pre * 32;
        #pragma unroll
        for (int i = 0; i < 4; ++i) {
            int e = tid + i * 256, row = e >> 3, g = e & 7;
            cp16(sA + row * 36 + g * 4, X + (size_t)(bm + row) * K + kt + g * 4);
            cp16(sB + row * 36 + g * 4, W + (size_t)(bn + row) * K + kt + g * 4);
        }
        CP_COMMIT();
    }

    int p = 0;
    for (int ki = 0; ki < 32; ++ki) {
        if (ki == 31) { CP_WAIT0(); } else { CP_WAIT1(); }
        __syncthreads();

        const uint32_t sAa = smem_u32(smem + p * GEMM_BUF) + aoff;
        const uint32_t sBa = smem_u32(smem + p * GEMM_BUF + 4608) + boff;

        uint32_t af[4][4], bf[4][2];
        #pragma unroll
        for (int mt = 0; mt < 4; ++mt)
            ldsm_x4(af[mt], sAa + mt * (16 * 36 * 4));
        #pragma unroll
        for (int ntp = 0; ntp < 2; ++ntp) {
            uint32_t t[4];
            ldsm_x4(t, sBa + ntp * (16 * 36 * 4));
            bf[2 * ntp][0]     = t[0];
            bf[2 * ntp][1]     = t[1];
            bf[2 * ntp + 1][0] = t[2];
            bf[2 * ntp + 1][1] = t[3];
        }

        if (ki + 2 < 32) {
            int nb = (p + 2) % GEMM_STAGES;
            float* sA = smem + nb * GEMM_BUF;
            float* sB = sA + 4608;
            int kt = (ki + 2) * 32;
            #pragma unroll
            for (int i = 0; i < 4; ++i) {
                int e = tid + i * 256, row = e >> 3, g = e & 7;
                cp16(sA + row * 36 + g * 4, X + (size_t)(bm + row) * K + kt + g * 4);
                cp16(sB + row * 36 + g * 4, W + (size_t)(bn + row) * K + kt + g * 4);
            }
            CP_COMMIT();
        }

        #pragma unroll
        for (int kk = 0; kk < 4; ++kk) {
            if (kk > 0) {
                #pragma unroll
                for (int mt = 0; mt < 4; ++mt)
                    ldsm_x4(af[mt], sAa + mt * (16 * 36 * 4) + kk * 32);
                #pragma unroll
                for (int ntp = 0; ntp < 2; ++ntp) {
                    uint32_t t[4];
                    ldsm_x4(t, sBa + ntp * (16 * 36 * 4) + kk * 32);
                    bf[2 * ntp][0]     = t[0];
                    bf[2 * ntp][1]     = t[1];
                    bf[2 * ntp + 1][0] = t[2];
                    bf[2 * ntp + 1][1] = t[3];
                }
            }
            #pragma unroll
            for (int mt = 0; mt < 4; ++mt)
                #pragma unroll
                for (int nt = 0; nt < 4; ++nt)
                    mma8(acc[mt][nt], af[mt], bf[nt]);
        }
        p = (p + 1) % GEMM_STAGES;
    }

    // epilogue
    #pragma unroll
    for (int mt = 0; mt < 4; ++mt) {
        int row0 = bm + wm * 64 + mt * 16 + r;
        #pragma unroll
        for (int nt = 0; nt < 4; ++nt) {
            int col = bn + wn * 32 + nt * 8 + 2 * c;
            float b0 = __ldg(bias + col);
            float b1 = __ldg(bias + col + 1);
            if (MODE == 0) {
                float2 v0 = make_float2(acc[mt][nt][0] + b0, acc[mt][nt][1] + b1);
                float2 v1 = make_float2(acc[mt][nt][2] + b0, acc[mt][nt][3] + b1);
                *reinterpret_cast<float2*>(out + (size_t)row0 * N + col)       = v0;
                *reinterpret_cast<float2*>(out + (size_t)(row0 + 8) * N + col) = v1;
            } else {
                float2 v0 = make_float2(tf32r(acc[mt][nt][0] + b0), tf32r(acc[mt][nt][1] + b1));
                float2 v1 = make_float2(tf32r(acc[mt][nt][2] + b0), tf32r(acc[mt][nt][3] + b1));
                int bb = row0 >> 11;
                int l0 = row0 & (SEQ - 1);
                int h  = col >> 6;
                int dh = col & 63;
                size_t d0 = ((size_t)(bb * NHEADS + h) * SEQ + l0) * HDIM + dh;
                *reinterpret_cast<float2*>(out + d0)            = v0;
                *reinterpret_cast<float2*>(out + d0 + 8 * HDIM) = v1;
            }
        }
    }
}

// Fused Q/K/V projection: blockIdx.z in {0,1,2} selects the GEMM.
__global__ __launch_bounds__(256) void gemm_qkv(
    const float* __restrict__ X0, const float* __restrict__ X1,
    const float* __restrict__ X2, const float* __restrict__ Wbase,
    const float* __restrict__ b0, const float* __restrict__ b1,
    const float* __restrict__ b2,
    float* __restrict__ o0, float* __restrict__ o1, float* __restrict__ o2)
{
    extern __shared__ float smem[];
    const int z = blockIdx.z;
    const float* X  = (z == 0) ? X0 : (z == 1) ? X1 : X2;
    const float* bi = (z == 0) ? b0 : (z == 1) ? b1 : b2;
    float*       o  = (z == 0) ? o0 : (z == 1) ? o1 : o2;
    gemm_body<1>(X, Wbase + (size_t)z * EE, bi, o, smem,
                 blockIdx.y * 128, blockIdx.x * 128);
}

__global__ __launch_bounds__(256) void gemm_o(
    const float* __restrict__ X, const float* __restrict__ W,
    const float* __restrict__ bias, float* __restrict__ out)
{
    extern __shared__ float smem[];
    gemm_body<0>(X, W, bias, out, smem, blockIdx.y * 128, blockIdx.x * 128);
}

// ---------------- causal flash attention ----------------
// 64-row q tiles, 16 q-rows/warp (low-register layout), 3 CTAs/SM for latency
// hiding. K stride 68 (LDSM conflict-free); V stride 72 (conflict-free scalar
// PV loads); PV redistribution via warp shuffles.
#define ATTN_KS   68
#define ATTN_VS   72
#define ATTN_KB   (64 * ATTN_KS)             // 4352 floats
#define ATTN_BUF  (ATTN_KB + 64 * ATTN_VS)   // 8960 floats per KV buffer
#define ATTN_SMEM (2 * ATTN_BUF * 4)         // 71680 bytes
#define SM_C 0.18033688011112042f            // (1/sqrt(64)) * log2(e)

__global__ __launch_bounds__(128, 3) void attn_kernel(float* __restrict__ outAO)
{
    extern __shared__ float sm[];

    const int tid  = threadIdx.x;
    const int lane = tid & 31;
    const int wid  = tid >> 5;            // 4 warps, 16 q rows each -> 64-row tile
    const int r    = lane >> 2;
    const int c    = lane & 3;
    const int lrow = lane & 7;
    const int grp  = lane >> 3;
    const int qt   = 31 - (int)blockIdx.x;   // heavy tiles first (0..31)
    const int bh   = blockIdx.y;

    const size_t base = (size_t)bh * SEQ * HDIM;
    const float* Qp = g_Q + base;
    const float* Kp = g_K + base;
    const float* Vp = g_V + base;

    const uint32_t koff = (((grp >> 1) * 8 + lrow) * ATTN_KS + (grp & 1) * 4) * 4;

    // ---- stage Q (64 rows), read fragments ----
    #pragma unroll
    for (int i = 0; i < 8; ++i) {
        int e = tid + i * 128, row = e >> 4, g = e & 15;
        cp16(sm + row * ATTN_KS + g * 4, Qp + (size_t)(qt * 64 + row) * HDIM + g * 4);
    }
    CP_COMMIT();
    CP_WAIT0();
    __syncthreads();

    uint32_t qa[8][4];
    {
        int row0 = wid * 16 + r;
        #pragma unroll
        for (int kk = 0; kk < 8; ++kk) {
            qa[kk][0] = __float_as_uint(sm[row0 * ATTN_KS + kk * 8 + c]);
            qa[kk][1] = __float_as_uint(sm[(row0 + 8) * ATTN_KS + kk * 8 + c]);
            qa[kk][2] = __float_as_uint(sm[row0 * ATTN_KS + kk * 8 + c + 4]);
            qa[kk][3] = __float_as_uint(sm[(row0 + 8) * ATTN_KS + kk * 8 + c + 4]);
        }
    }
    __syncthreads();

    float o[8][4];
    #pragma unroll
    for (int dt = 0; dt < 8; ++dt)
        #pragma unroll
        for (int e = 0; e < 4; ++e) o[dt][e] = 0.f;

    float m0 = -1e30f, m1 = -1e30f, l0 = 0.f, l1 = 0.f;
    const int qrow = qt * 64 + wid * 16 + r;   // rows qrow and qrow+8
    const int srcA = (lane & ~3) | (c >> 1);
    const int srcB = srcA + 2;
    const bool odd = (c & 1);
    const int jt_end = qt;

    {
        float* kb = sm;
        float* vb = sm + ATTN_KB;
        #pragma unroll
        for (int i = 0; i < 8; ++i) {
            int e = tid + i * 128, row = e >> 4, g = e & 15;
            cp16(kb + row * ATTN_KS + g * 4, Kp + (size_t)row * HDIM + g * 4);
            cp16(vb + row * ATTN_VS + g * 4, Vp + (size_t)row * HDIM + g * 4);
        }
        CP_COMMIT();
    }

    int p = 0;
    for (int jt = 0; jt <= jt_end; ++jt) {
        CP_WAIT0();
        __syncthreads();

        const float* kS = sm + p * ATTN_BUF;
        const float* vS = kS + ATTN_KB;
        const uint32_t kSa = smem_u32(kS) + koff;

        // ---- S = Q K^T : 16 x 64 per warp; K-frags via ldmatrix x4 ----
        float s[8][4];
        #pragma unroll
        for (int nt = 0; nt < 8; ++nt)
            #pragma unroll
            for (int e = 0; e < 4; ++e) s[nt][e] = 0.f;

        #pragma unroll
        for (int kk = 0; kk < 8; ++kk) {
            #pragma unroll
            for (int ntp = 0; ntp < 4; ++ntp) {
                uint32_t t[4];
                ldsm_x4(t, kSa + ntp * (16 * ATTN_KS * 4) + kk * 32);
                mma8(s[2 * ntp],     qa[kk], &t[0]);
                mma8(s[2 * ntp + 1], qa[kk], &t[2]);
            }
        }

        // prefetch next KV tile AFTER the S MMAs have been issued
        if (jt + 1 <= jt_end) {
            float* kb = sm + (p ^ 1) * ATTN_BUF;
            float* vb = kb + ATTN_KB;
            #pragma unroll
            for (int i = 0; i < 8; ++i) {
                int e = tid + i * 128, row = e >> 4, g = e & 15;
                cp16(kb + row * ATTN_KS + g * 4, Kp + (size_t)((jt + 1) * 64 + row) * HDIM + g * 4);
                cp16(vb + row * ATTN_VS + g * 4, Vp + (size_t)((jt + 1) * 64 + row) * HDIM + g * 4);
            }
            CP_COMMIT();
        }

        // ---- causal mask (only the diagonal tile jt == qt) ----
        if (jt == qt) {
            #pragma unroll
            for (int nt = 0; nt < 8; ++nt) {
                int kc = jt * 64 + nt * 8 + 2 * c;
                if (kc > qrow)         s[nt][0] = -1e30f;
                if (kc + 1 > qrow)     s[nt][1] = -1e30f;
                if (kc > qrow + 8)     s[nt][2] = -1e30f;
                if (kc + 1 > qrow + 8) s[nt][3] = -1e30f;
            }
        }

        // ---- online softmax (exp2 domain) ----
        float rmax0 = -1e30f, rmax1 = -1e30f;
        #pragma unroll
        for (int nt = 0; nt < 8; ++nt) {
            rmax0 = fmaxf(rmax0, fmaxf(s[nt][0], s[nt][1]));
            rmax1 = fmaxf(rmax1, fmaxf(s[nt][2], s[nt][3]));
        }
        rmax0 = fmaxf(rmax0, __shfl_xor_sync(0xFFFFFFFFu, rmax0, 1));
        rmax0 = fmaxf(rmax0, __shfl_xor_sync(0xFFFFFFFFu, rmax0, 2));
        rmax1 = fmaxf(rmax1, __shfl_xor_sync(0xFFFFFFFFu, rmax1, 1));
        rmax1 = fmaxf(rmax1, __shfl_xor_sync(0xFFFFFFFFu, rmax1, 2));

        float mn0 = fmaxf(m0, rmax0);
        float mn1 = fmaxf(m1, rmax1);
        float f0 = ex2((m0 - mn0) * SM_C);
        float f1 = ex2((m1 - mn1) * SM_C);
        float mc0 = mn0 * SM_C, mc1 = mn1 * SM_C;
        float rs0 = 0.f, rs1 = 0.f;
        #pragma unroll
        for (int nt = 0; nt < 8; ++nt) {
            s[nt][0] = ex2(fmaf(s[nt][0], SM_C, -mc0));
            s[nt][1] = ex2(fmaf(s[nt][1], SM_C, -mc0));
            s[nt][2] = ex2(fmaf(s[nt][2], SM_C, -mc1));
            s[nt][3] = ex2(fmaf(s[nt][3], SM_C, -mc1));
            rs0 += s[nt][0] + s[nt][1];
            rs1 += s[nt][2] + s[nt][3];
        }
        rs0 += __shfl_xor_sync(0xFFFFFFFFu, rs0, 1);
        rs0 += __shfl_xor_sync(0xFFFFFFFFu, rs0, 2);
        rs1 += __shfl_xor_sync(0xFFFFFFFFu, rs1, 1);
        rs1 += __shfl_xor_sync(0xFFFFFFFFu, rs1, 2);
        l0 = l0 * f0 + rs0;
        l1 = l1 * f1 + rs1;
        m0 = mn0; m1 = mn1;
        #pragma unroll
        for (int dt = 0; dt < 8; ++dt) {
            o[dt][0] *= f0; o[dt][1] *= f0;
            o[dt][2] *= f1; o[dt][3] *= f1;
        }

        // ---- O += P V : redistribute P (C-frag -> A-frag) via shuffles ----
        #pragma unroll
        for (int kk = 0; kk < 8; ++kk) {
            float x0 = __shfl_sync(0xFFFFFFFFu, s[kk][0], srcA);
            float x1 = __shfl_sync(0xFFFFFFFFu, s[kk][1], srcA);
            float y0 = __shfl_sync(0xFFFFFFFFu, s[kk][2], srcA);
            float y1 = __shfl_sync(0xFFFFFFFFu, s[kk][3], srcA);
            float z0 = __shfl_sync(0xFFFFFFFFu, s[kk][0], srcB);
            float z1 = __shfl_sync(0xFFFFFFFFu, s[kk][1], srcB);
            float w0 = __shfl_sync(0xFFFFFFFFu, s[kk][2], srcB);
            float w1 = __shfl_sync(0xFFFFFFFFu, s[kk][3], srcB);
            uint32_t pa[4];
            pa[0] = f2tf(odd ? x1 : x0);
            pa[1] = f2tf(odd ? y1 : y0);
            pa[2] = f2tf(odd ? z1 : z0);
            pa[3] = f2tf(odd ? w1 : w0);
            #pragma unroll
            for (int dt = 0; dt < 8; ++dt) {
                uint32_t vb[2];
                vb[0] = __float_as_uint(vS[(kk * 8 + c) * ATTN_VS + dt * 8 + r]);
                vb[1] = __float_as_uint(vS[(kk * 8 + c + 4) * ATTN_VS + dt * 8 + r]);
                mma8(o[dt], pa, vb);
            }
        }
        p ^= 1;
    }

    // ---- epilogue ----
    int b = bh >> 4, h = bh & 15;
    float il0 = 1.f / l0, il1 = 1.f / l1;
    float* op  = outAO + ((size_t)(b * SEQ + qrow)) * EMBED + h * HDIM;
    float* op1 = op + (size_t)8 * EMBED;
    #pragma unroll
    for (int dt = 0; dt < 8; ++dt) {
        float2 v0 = make_float2(tf32r(o[dt][0] * il0), tf32r(o[dt][1] * il0));
        float2 v1 = make_float2(tf32r(o[dt][2] * il1), tf32r(o[dt][3] * il1));
        *reinterpret_cast<float2*>(op  + dt * 8 + 2 * c) = v0;
        *reinterpret_cast<float2*>(op1 + dt * 8 + 2 * c) = v1;
    }
}

// ---------------- launch ----------------
extern "C" void kernel_launch(void* const* d_in, const int* in_sizes, int n_in,
                              void* d_out, int out_size)
{
    (void)in_sizes; (void)n_in; (void)out_size;
    const float* query = (const float*)d_in[0];
    const float* key   = (const float*)d_in[1];
    const float* value = (const float*)d_in[2];
    const float* Wq    = (const float*)d_in[3];
    const float* bq    = (const float*)d_in[4];
    const float* Wk    = (const float*)d_in[5];
    const float* bk    = (const float*)d_in[6];
    const float* Wv    = (const float*)d_in[7];
    const float* bv    = (const float*)d_in[8];
    const float* Wo    = (const float*)d_in[9];
    const float* bo    = (const float*)d_in[10];
    float* out = (float*)d_out;

    cudaFuncSetAttribute(gemm_qkv, cudaFuncAttributeMaxDynamicSharedMemorySize, GEMM_SMEM);
    cudaFuncSetAttribute(gemm_o,   cudaFuncAttributeMaxDynamicSharedMemorySize, GEMM_SMEM);
    cudaFuncSetAttribute(attn_kernel, cudaFuncAttributeMaxDynamicSharedMemorySize, ATTN_SMEM);

    float *gq, *gk, *gv, *grq, *grk, *grv, *grw;
    cudaGetSymbolAddress((void**)&gq,  g_Q);
    cudaGetSymbolAddress((void**)&gk,  g_K);
    cudaGetSymbolAddress((void**)&gv,  g_V);
    cudaGetSymbolAddress((void**)&grq, g_rq);
    cudaGetSymbolAddress((void**)&grk, g_rk);
    cudaGetSymbolAddress((void**)&grv, g_rv);
    cudaGetSymbolAddress((void**)&grw, g_rw);

    const int n4x = MROWS * EMBED / 4;
    const int n4w = EE / 4;

    // Single fused rounding launch (7 tensors via blockIdx.y)
    round_all_kernel<<<dim3(1024, 7), 256>>>(
        (const float4*)query, (float4*)grq,
        (const float4*)key,   (float4*)grk,
        (const float4*)value, (float4*)grv,
        (const float4*)Wq, (const float4*)Wk, (const float4*)Wv, (const float4*)Wo,
        (float4*)grw, n4x, n4w);

    // Fused Q/K/V projections in one launch
    gemm_qkv<<<dim3(8, 64, 3), 256, GEMM_SMEM>>>(
        grq, grk, grv, grw, bq, bk, bv, gq, gk, gv);

    // attention output reuses g_rq (Q projection already consumed it)
    attn_kernel<<<dim3(32, 64), dim3(128), ATTN_SMEM>>>(grq);

    gemm_o<<<dim3(8, 64), 256, GEMM_SMEM>>>(grq, grw + 3 * EE, bo, out);
}

// round 15
// speedup vs baseline: 1.0079x; 1.0079x over previous
#include <cuda_runtime.h>
#include <cstdint>

#define EMBED   1024
#define NHEADS  16
#define HDIM    64
#define BATCH   4
#define SEQ     2048
#define MROWS   (BATCH * SEQ)                   // 8192
#define HEADEL  (BATCH * NHEADS * SEQ * HDIM)   // 8388608
#define EE      (EMBED * EMBED)

// Scratch (static device globals: allocation-free rule).
__device__ float g_Q[HEADEL];
__device__ float g_K[HEADEL];
__device__ float g_V[HEADEL];
__device__ float g_rq[MROWS * EMBED];
__device__ float g_rk[MROWS * EMBED];
__device__ float g_rv[MROWS * EMBED];
__device__ float g_rw[4 * EE];

// ---------------- helpers ----------------
__device__ __forceinline__ uint32_t f2tf(float x) {
    uint32_t u;
    asm("cvt.rna.tf32.f32 %0, %1;" : "=r"(u) : "f"(x));
    return u;
}
__device__ __forceinline__ float tf32r(float x) {
    return __uint_as_float(f2tf(x));
}
__device__ __forceinline__ float ex2(float x) {
    float y;
    asm("ex2.approx.f32 %0, %1;" : "=f"(y) : "f"(x));
    return y;
}
// NOTE: non-volatile — mma.sync is a pure register op; letting the compiler
// reschedule it against (volatile) LDSMs enables software pipelining without
// extra register buffers. Per-accumulator order is fixed by the d-reg chain.
__device__ __forceinline__ void mma8(float* d, const uint32_t* a, const uint32_t* b) {
    asm("mma.sync.aligned.m16n8k8.row.col.f32.tf32.tf32.f32 "
        "{%0,%1,%2,%3},{%4,%5,%6,%7},{%8,%9},{%0,%1,%2,%3};\n"
        : "+f"(d[0]), "+f"(d[1]), "+f"(d[2]), "+f"(d[3])
        : "r"(a[0]), "r"(a[1]), "r"(a[2]), "r"(a[3]), "r"(b[0]), "r"(b[1]));
}
__device__ __forceinline__ void cp16(float* s, const float* g) {
    uint32_t sa = (uint32_t)__cvta_generic_to_shared(s);
    asm volatile("cp.async.cg.shared.global [%0], [%1], 16;" :: "r"(sa), "l"(g));
}
#define CP_COMMIT() asm volatile("cp.async.commit_group;")
#define CP_WAIT0()  asm volatile("cp.async.wait_group 0;")
#define CP_WAIT1()  asm volatile("cp.async.wait_group 1;")

__device__ __forceinline__ uint32_t smem_u32(const void* p) {
    return (uint32_t)__cvta_generic_to_shared(p);
}
// ldmatrix x4 of 8x8 b32 tiles (b16 form, no trans; dtype-agnostic 16B row moves)
__device__ __forceinline__ void ldsm_x4(uint32_t* r, uint32_t addr) {
    asm volatile("ldmatrix.sync.aligned.m8n8.x4.shared.b16 {%0,%1,%2,%3}, [%4];"
                 : "=r"(r[0]), "=r"(r[1]), "=r"(r[2]), "=r"(r[3]) : "r"(addr));
}

// ---------------- single fused pre-round to tf32 (rna), 7 tensors ------------
__global__ void round_all_kernel(const float4* __restrict__ a0, float4* __restrict__ d0,
                                 const float4* __restrict__ a1, float4* __restrict__ d1,
                                 const float4* __restrict__ a2, float4* __restrict__ d2,
                                 const float4* __restrict__ w0, const float4* __restrict__ w1,
                                 const float4* __restrict__ w2, const float4* __restrict__ w3,
                                 float4* __restrict__ wdst, int n4x, int n4w)
{
    const int y = blockIdx.y;
    const float4* src;
    float4* dst;
    int n4;
    if (y < 3) {
        src = (y == 0) ? a0 : (y == 1) ? a1 : a2;
        dst = (y == 0) ? d0 : (y == 1) ? d1 : d2;
        n4  = n4x;
    } else {
        src = (y == 3) ? w0 : (y == 4) ? w1 : (y == 5) ? w2 : w3;
        dst = wdst + (size_t)(y - 3) * (EE / 4);
        n4  = n4w;
    }
    for (int i = blockIdx.x * blockDim.x + threadIdx.x; i < n4;
         i += gridDim.x * blockDim.x) {
        float4 v = src[i];
        dst[i] = make_float4(tf32r(v.x), tf32r(v.y), tf32r(v.z), tf32r(v.w));
    }
}

// ---------------- TN GEMM body: out = X @ W^T + bias (mma.sync + ldmatrix) ---
// 3-stage cp.async, K=32 chunks, 2 CTA/SM (108 KB smem) — measured-best config.
#define GEMM_BUF 9216            // floats per buffer (sA 128*36 + sB 128*36)
#define GEMM_STAGES 3
#define GEMM_SMEM (GEMM_STAGES * GEMM_BUF * 4)

template<int MODE>
__device__ __forceinline__ void gemm_body(const float* __restrict__ X,
                                          const float* __restrict__ W,
                                          const float* __restrict__ bias,
                                          float* __restrict__ out,
                                          float* smem, int bm, int bn)
{
    constexpr int K = EMBED, N = EMBED;
    const int tid  = threadIdx.x;
    const int lane = tid & 31;
    const int wid  = tid >> 5;
    const int wm   = wid & 1;
    const int wn   = wid >> 1;
    const int r    = lane >> 2;
    const int c    = lane & 3;
    const int lrow = lane & 7;
    const int grp  = lane >> 3;

    const uint32_t aoff = ((wm * 64 + (grp & 1) * 8 + lrow) * 36 + (grp >> 1) * 4) * 4;
    const uint32_t boff = ((wn * 32 + (grp >> 1) * 8 + lrow) * 36 + (grp & 1) * 4) * 4;

    float acc[4][4][4];
    #pragma unroll
    for (int mt = 0; mt < 4; ++mt)
        #pragma unroll
        for (int nt = 0; nt < 4; ++nt)
            #pragma unroll
            for (int e = 0; e < 4; ++e) acc[mt][nt][e] = 0.f;

    #pragma unroll
    for (int pre = 0; pre < 2; ++pre) {
        float* sA = smem + pre * GEMM_BUF;
        float* sB = sA + 4608;
        int kt = pre * 32;
        #pragma unroll
        for (int i = 0; i < 4; ++i) {
            int e = tid + i * 256, row = e >> 3, g = e & 7;
            cp16(sA + row * 36 + g * 4, X + (size_t)(bm + row) * K + kt + g * 4);
            cp16(sB + row * 36 + g * 4, W + (size_t)(bn + row) * K + kt + g * 4);
        }
        CP_COMMIT();
    }

    int p = 0;
    for (int ki = 0; ki < 32; ++ki) {
        if (ki == 31) { CP_WAIT0(); } else { CP_WAIT1(); }
        __syncthreads();

        const uint32_t sAa = smem_u32(smem + p * GEMM_BUF) + aoff;
        const uint32_t sBa = smem_u32(smem + p * GEMM_BUF + 4608) + boff;

        uint32_t af[4][4], bf[4][2];
        #pragma unroll
        for (int mt = 0; mt < 4; ++mt)
            ldsm_x4(af[mt], sAa + mt * (16 * 36 * 4));
        #pragma unroll
        for (int ntp = 0; ntp < 2; ++ntp) {
            uint32_t t[4];
            ldsm_x4(t, sBa + ntp * (16 * 36 * 4));
            bf[2 * ntp][0]     = t[0];
            bf[2 * ntp][1]     = t[1];
            bf[2 * ntp + 1][0] = t[2];
            bf[2 * ntp + 1][1] = t[3];
        }

        if (ki + 2 < 32) {
            int nb = (p + 2) % GEMM_STAGES;
            float* sA = smem + nb * GEMM_BUF;
            float* sB = sA + 4608;
            int kt = (ki + 2) * 32;
            #pragma unroll
            for (int i = 0; i < 4; ++i) {
                int e = tid + i * 256, row = e >> 3, g = e & 7;
                cp16(sA + row * 36 + g * 4, X + (size_t)(bm + row) * K + kt + g * 4);
                cp16(sB + row * 36 + g * 4, W + (size_t)(bn + row) * K + kt + g * 4);
            }
            CP_COMMIT();
        }

        #pragma unroll
        for (int kk = 0; kk < 4; ++kk) {
            if (kk > 0) {
                #pragma unroll
                for (int mt = 0; mt < 4; ++mt)
                    ldsm_x4(af[mt], sAa + mt * (16 * 36 * 4) + kk * 32);
                #pragma unroll
                for (int ntp = 0; ntp < 2; ++ntp) {
                    uint32_t t[4];
                    ldsm_x4(t, sBa + ntp * (16 * 36 * 4) + kk * 32);
                    bf[2 * ntp][0]     = t[0];
                    bf[2 * ntp][1]     = t[1];
                    bf[2 * ntp + 1][0] = t[2];
                    bf[2 * ntp + 1][1] = t[3];
                }
            }
            #pragma unroll
            for (int mt = 0; mt < 4; ++mt)
                #pragma unroll
                for (int nt = 0; nt < 4; ++nt)
                    mma8(acc[mt][nt], af[mt], bf[nt]);
        }
        p = (p + 1) % GEMM_STAGES;
    }

    // epilogue
    #pragma unroll
    for (int mt = 0; mt < 4; ++mt) {
        int row0 = bm + wm * 64 + mt * 16 + r;
        #pragma unroll
        for (int nt = 0; nt < 4; ++nt) {
            int col = bn + wn * 32 + nt * 8 + 2 * c;
            float b0 = __ldg(bias + col);
            float b1 = __ldg(bias + col + 1);
            if (MODE == 0) {
                float2 v0 = make_float2(acc[mt][nt][0] + b0, acc[mt][nt][1] + b1);
                float2 v1 = make_float2(acc[mt][nt][2] + b0, acc[mt][nt][3] + b1);
                *reinterpret_cast<float2*>(out + (size_t)row0 * N + col)       = v0;
                *reinterpret_cast<float2*>(out + (size_t)(row0 + 8) * N + col) = v1;
            } else {
                float2 v0 = make_float2(tf32r(acc[mt][nt][0] + b0), tf32r(acc[mt][nt][1] + b1));
                float2 v1 = make_float2(tf32r(acc[mt][nt][2] + b0), tf32r(acc[mt][nt][3] + b1));
                int bb = row0 >> 11;
                int l0 = row0 & (SEQ - 1);
                int h  = col >> 6;
                int dh = col & 63;
                size_t d0 = ((size_t)(bb * NHEADS + h) * SEQ + l0) * HDIM + dh;
                *reinterpret_cast<float2*>(out + d0)            = v0;
                *reinterpret_cast<float2*>(out + d0 + 8 * HDIM) = v1;
            }
        }
    }
}

// Fused Q/K/V projection: blockIdx.z in {0,1,2} selects the GEMM.
__global__ __launch_bounds__(256) void gemm_qkv(
    const float* __restrict__ X0, const float* __restrict__ X1,
    const float* __restrict__ X2, const float* __restrict__ Wbase,
    const float* __restrict__ b0, const float* __restrict__ b1,
    const float* __restrict__ b2,
    float* __restrict__ o0, float* __restrict__ o1, float* __restrict__ o2)
{
    extern __shared__ float smem[];
    const int z = blockIdx.z;
    const float* X  = (z == 0) ? X0 : (z == 1) ? X1 : X2;
    const float* bi = (z == 0) ? b0 : (z == 1) ? b1 : b2;
    float*       o  = (z == 0) ? o0 : (z == 1) ? o1 : o2;
    gemm_body<1>(X, Wbase + (size_t)z * EE, bi, o, smem,
                 blockIdx.y * 128, blockIdx.x * 128);
}

__global__ __launch_bounds__(256) void gemm_o(
    const float* __restrict__ X, const float* __restrict__ W,
    const float* __restrict__ bias, float* __restrict__ out)
{
    extern __shared__ float smem[];
    gemm_body<0>(X, W, bias, out, smem, blockIdx.y * 128, blockIdx.x * 128);
}

// ---------------- causal flash attention ----------------
// 128-row q tiles, 32 q-rows/warp, 2 CTAs/SM. K stride 68 (LDSM conflict-free);
// V stride 72 (conflict-free scalar PV loads); P staged per-warp at stride 68
// and read back via ldmatrix A-frags.
#define ATTN_KS   68
#define ATTN_VS   72
#define ATTN_KB   (64 * ATTN_KS)             // 4352 floats
#define ATTN_BUF  (ATTN_KB + 64 * ATTN_VS)   // 8960 floats per KV buffer
#define ATTN_PS   (32 * 68)                  // P region floats per warp
#define ATTN_SMEM ((2 * ATTN_BUF + 4 * ATTN_PS) * 4)   // 106496 bytes
#define SM_C 0.18033688011112042f            // (1/sqrt(64)) * log2(e)

__global__ __launch_bounds__(128, 2) void attn_kernel(float* __restrict__ outAO)
{
    extern __shared__ float sm[];

    const int tid  = threadIdx.x;
    const int lane = tid & 31;
    const int wid  = tid >> 5;            // 4 warps, 32 q rows each
    const int r    = lane >> 2;
    const int c    = lane & 3;
    const int lrow = lane & 7;
    const int grp  = lane >> 3;
    const int qt   = 15 - (int)blockIdx.x;
    const int bh   = blockIdx.y;

    const size_t base = (size_t)bh * SEQ * HDIM;
    const float* Qp = g_Q + base;
    const float* Kp = g_K + base;
    const float* Vp = g_V + base;

    const uint32_t koff = (((grp >> 1) * 8 + lrow) * ATTN_KS + (grp & 1) * 4) * 4;
    float* pS = sm + 2 * ATTN_BUF + wid * ATTN_PS;
    const uint32_t pSa = smem_u32(pS) + (((grp & 1) * 8 + lrow) * 68 + (grp >> 1) * 4) * 4;

    // ---- stage Q (128 rows), read fragments ----
    #pragma unroll
    for (int i = 0; i < 16; ++i) {
        int e = tid + i * 128, row = e >> 4, g = e & 15;
        cp16(sm + row * ATTN_KS + g * 4, Qp + (size_t)(qt * 128 + row) * HDIM + g * 4);
    }
    CP_COMMIT();
    CP_WAIT0();
    __syncthreads();

    uint32_t qa[2][8][4];
    #pragma unroll
    for (int mt = 0; mt < 2; ++mt) {
        int row0 = wid * 32 + mt * 16 + r;
        #pragma unroll
        for (int kk = 0; kk < 8; ++kk) {
            qa[mt][kk][0] = __float_as_uint(sm[row0 * ATTN_KS + kk * 8 + c]);
            qa[mt][kk][1] = __float_as_uint(sm[(row0 + 8) * ATTN_KS + kk * 8 + c]);
            qa[mt][kk][2] = __float_as_uint(sm[row0 * ATTN_KS + kk * 8 + c + 4]);
            qa[mt][kk][3] = __float_as_uint(sm[(row0 + 8) * ATTN_KS + kk * 8 + c + 4]);
        }
    }
    __syncthreads();

    float o[2][8][4];
    #pragma unroll
    for (int mt = 0; mt < 2; ++mt)
        #pragma unroll
        for (int dt = 0; dt < 8; ++dt)
            #pragma unroll
            for (int e = 0; e < 4; ++e) o[mt][dt][e] = 0.f;

    float mrow[2][2], lrow2[2][2];
    #pragma unroll
    for (int mt = 0; mt < 2; ++mt) {
        mrow[mt][0] = -1e30f; mrow[mt][1] = -1e30f;
        lrow2[mt][0] = 0.f;   lrow2[mt][1] = 0.f;
    }

    const int qr[2] = { qt * 128 + wid * 32 + r, qt * 128 + wid * 32 + 16 + r };
    const int jt_end = 2 * qt + 1;

    {
        float* kb = sm;
        float* vb = sm + ATTN_KB;
        #pragma unroll
        for (int i = 0; i < 8; ++i) {
            int e = tid + i * 128, row = e >> 4, g = e & 15;
            cp16(kb + row * ATTN_KS + g * 4, Kp + (size_t)row * HDIM + g * 4);
            cp16(vb + row * ATTN_VS + g * 4, Vp + (size_t)row * HDIM + g * 4);
        }
        CP_COMMIT();
    }

    int p = 0;
    for (int jt = 0; jt <= jt_end; ++jt) {
        CP_WAIT0();
        __syncthreads();

        const float* kS = sm + p * ATTN_BUF;
        const float* vS = kS + ATTN_KB;
        const uint32_t kSa = smem_u32(kS) + koff;

        // ---- S = Q K^T : K-frags via ldmatrix x4 (nt pairs) ----
        float s[2][8][4];
        #pragma unroll
        for (int mt = 0; mt < 2; ++mt)
            #pragma unroll
            for (int nt = 0; nt < 8; ++nt)
                #pragma unroll
                for (int e = 0; e < 4; ++e) s[mt][nt][e] = 0.f;

        #pragma unroll
        for (int kk = 0; kk < 8; ++kk) {
            #pragma unroll
            for (int ntp = 0; ntp < 4; ++ntp) {
                uint32_t t[4];
                ldsm_x4(t, kSa + ntp * (16 * ATTN_KS * 4) + kk * 32);
                mma8(s[0][2 * ntp],     qa[0][kk], &t[0]);
                mma8(s[1][2 * ntp],     qa[1][kk], &t[0]);
                mma8(s[0][2 * ntp + 1], qa[0][kk], &t[2]);
                mma8(s[1][2 * ntp + 1], qa[1][kk], &t[2]);
            }
        }

        // prefetch next KV tile AFTER the S MMAs have been issued
        if (jt + 1 <= jt_end) {
            float* kb = sm + (p ^ 1) * ATTN_BUF;
            float* vb = kb + ATTN_KB;
            #pragma unroll
            for (int i = 0; i < 8; ++i) {
                int e = tid + i * 128, row = e >> 4, g = e & 15;
                cp16(kb + row * ATTN_KS + g * 4, Kp + (size_t)((jt + 1) * 64 + row) * HDIM + g * 4);
                cp16(vb + row * ATTN_VS + g * 4, Vp + (size_t)((jt + 1) * 64 + row) * HDIM + g * 4);
            }
            CP_COMMIT();
        }

        // ---- causal mask ----
        if (jt >= 2 * qt) {
            #pragma unroll
            for (int mt = 0; mt < 2; ++mt)
                #pragma unroll
                for (int nt = 0; nt < 8; ++nt) {
                    int kc = jt * 64 + nt * 8 + 2 * c;
                    if (kc > qr[mt])         s[mt][nt][0] = -1e30f;
                    if (kc + 1 > qr[mt])     s[mt][nt][1] = -1e30f;
                    if (kc > qr[mt] + 8)     s[mt][nt][2] = -1e30f;
                    if (kc + 1 > qr[mt] + 8) s[mt][nt][3] = -1e30f;
                }
        }

        // ---- online softmax (exp2 domain) ----
        #pragma unroll
        for (int mt = 0; mt < 2; ++mt) {
            float rmax0 = -1e30f, rmax1 = -1e30f;
            #pragma unroll
            for (int nt = 0; nt < 8; ++nt) {
                rmax0 = fmaxf(rmax0, fmaxf(s[mt][nt][0], s[mt][nt][1]));
                rmax1 = fmaxf(rmax1, fmaxf(s[mt][nt][2], s[mt][nt][3]));
            }
            rmax0 = fmaxf(rmax0, __shfl_xor_sync(0xFFFFFFFFu, rmax0, 1));
            rmax0 = fmaxf(rmax0, __shfl_xor_sync(0xFFFFFFFFu, rmax0, 2));
            rmax1 = fmaxf(rmax1, __shfl_xor_sync(0xFFFFFFFFu, rmax1, 1));
            rmax1 = fmaxf(rmax1, __shfl_xor_sync(0xFFFFFFFFu, rmax1, 2));

            float mn0 = fmaxf(mrow[mt][0], rmax0);
            float mn1 = fmaxf(mrow[mt][1], rmax1);
            float f0 = ex2((mrow[mt][0] - mn0) * SM_C);
            float f1 = ex2((mrow[mt][1] - mn1) * SM_C);
            float mc0 = mn0 * SM_C, mc1 = mn1 * SM_C;
            float rs0 = 0.f, rs1 = 0.f;
            #pragma unroll
            for (int nt = 0; nt < 8; ++nt) {
                s[mt][nt][0] = ex2(fmaf(s[mt][nt][0], SM_C, -mc0));
                s[mt][nt][1] = ex2(fmaf(s[mt][nt][1], SM_C, -mc0));
                s[mt][nt][2] = ex2(fmaf(s[mt][nt][2], SM_C, -mc1));
                s[mt][nt][3] = ex2(fmaf(s[mt][nt][3], SM_C, -mc1));
                rs0 += s[mt][nt][0] + s[mt][nt][1];
                rs1 += s[mt][nt][2] + s[mt][nt][3];
            }
            rs0 += __shfl_xor_sync(0xFFFFFFFFu, rs0, 1);
            rs0 += __shfl_xor_sync(0xFFFFFFFFu, rs0, 2);
            rs1 += __shfl_xor_sync(0xFFFFFFFFu, rs1, 1);
            rs1 += __shfl_xor_sync(0xFFFFFFFFu, rs1, 2);
            lrow2[mt][0] = lrow2[mt][0] * f0 + rs0;
            lrow2[mt][1] = lrow2[mt][1] * f1 + rs1;
            mrow[mt][0] = mn0; mrow[mt][1] = mn1;
            #pragma unroll
            for (int dt = 0; dt < 8; ++dt) {
                o[mt][dt][0] *= f0; o[mt][dt][1] *= f0;
                o[mt][dt][2] *= f1; o[mt][dt][3] *= f1;
            }
        }

        // ---- stage P (tf32) to per-warp smem, read back as A-frags ----
        #pragma unroll
        for (int mt = 0; mt < 2; ++mt)
            #pragma unroll
            for (int kk = 0; kk < 8; ++kk) {
                uint32_t* w0 = reinterpret_cast<uint32_t*>(
                    pS + (mt * 16 + r) * 68 + kk * 8 + 2 * c);
                w0[0] = f2tf(s[mt][kk][0]);
                w0[1] = f2tf(s[mt][kk][1]);
                uint32_t* w1 = reinterpret_cast<uint32_t*>(
                    pS + (mt * 16 + 8 + r) * 68 + kk * 8 + 2 * c);
                w1[0] = f2tf(s[mt][kk][2]);
                w1[1] = f2tf(s[mt][kk][3]);
            }
        __syncwarp();

        // ---- O += P V ----
        #pragma unroll
        for (int kk = 0; kk < 8; ++kk) {
            uint32_t pa0[4], pa1[4];
            ldsm_x4(pa0, pSa + kk * 32);
            ldsm_x4(pa1, pSa + 16 * 68 * 4 + kk * 32);
            #pragma unroll
            for (int dt = 0; dt < 8; ++dt) {
                uint32_t vb[2];
                vb[0] = __float_as_uint(vS[(kk * 8 + c) * ATTN_VS + dt * 8 + r]);
                vb[1] = __float_as_uint(vS[(kk * 8 + c + 4) * ATTN_VS + dt * 8 + r]);
                mma8(o[0][dt], pa0, vb);
                mma8(o[1][dt], pa1, vb);
            }
        }
        __syncwarp();
        p ^= 1;
    }

    // ---- epilogue ----
    int b = bh >> 4, h = bh & 15;
    #pragma unroll
    for (int mt = 0; mt < 2; ++mt) {
        float il0 = 1.f / lrow2[mt][0], il1 = 1.f / lrow2[mt][1];
        float* op  = outAO + ((size_t)(b * SEQ + qr[mt])) * EMBED + h * HDIM;
        float* op1 = op + (size_t)8 * EMBED;
        #pragma unroll
        for (int dt = 0; dt < 8; ++dt) {
            float2 v0 = make_float2(tf32r(o[mt][dt][0] * il0), tf32r(o[mt][dt][1] * il0));
            float2 v1 = make_float2(tf32r(o[mt][dt][2] * il1), tf32r(o[mt][dt][3] * il1));
            *reinterpret_cast<float2*>(op  + dt * 8 + 2 * c) = v0;
            *reinterpret_cast<float2*>(op1 + dt * 8 + 2 * c) = v1;
        }
    }
}

// ---------------- launch ----------------
extern "C" void kernel_launch(void* const* d_in, const int* in_sizes, int n_in,
                              void* d_out, int out_size)
{
    (void)in_sizes; (void)n_in; (void)out_size;
    const float* query = (const float*)d_in[0];
    const float* key   = (const float*)d_in[1];
    const float* value = (const float*)d_in[2];
    const float* Wq    = (const float*)d_in[3];
    const float* bq    = (const float*)d_in[4];
    const float* Wk    = (const float*)d_in[5];
    const float* bk    = (const float*)d_in[6];
    const float* Wv    = (const float*)d_in[7];
    const float* bv    = (const float*)d_in[8];
    const float* Wo    = (const float*)d_in[9];
    const float* bo    = (const float*)d_in[10];
    float* out = (float*)d_out;

    cudaFuncSetAttribute(gemm_qkv, cudaFuncAttributeMaxDynamicSharedMemorySize, GEMM_SMEM);
    cudaFuncSetAttribute(gemm_o,   cudaFuncAttributeMaxDynamicSharedMemorySize, GEMM_SMEM);
    cudaFuncSetAttribute(attn_kernel, cudaFuncAttributeMaxDynamicSharedMemorySize, ATTN_SMEM);

    float *gq, *gk, *gv, *grq, *grk, *grv, *grw;
    cudaGetSymbolAddress((void**)&gq,  g_Q);
    cudaGetSymbolAddress((void**)&gk,  g_K);
    cudaGetSymbolAddress((void**)&gv,  g_V);
    cudaGetSymbolAddress((void**)&grq, g_rq);
    cudaGetSymbolAddress((void**)&grk, g_rk);
    cudaGetSymbolAddress((void**)&grv, g_rv);
    cudaGetSymbolAddress((void**)&grw, g_rw);

    const int n4x = MROWS * EMBED / 4;
    const int n4w = EE / 4;

    // Single fused rounding launch (7 tensors via blockIdx.y)
    round_all_kernel<<<dim3(1024, 7), 256>>>(
        (const float4*)query, (float4*)grq,
        (const float4*)key,   (float4*)grk,
        (const float4*)value, (float4*)grv,
        (const float4*)Wq, (const float4*)Wk, (const float4*)Wv, (const float4*)Wo,
        (float4*)grw, n4x, n4w);

    // Fused Q/K/V projections in one launch
    gemm_qkv<<<dim3(8, 64, 3), 256, GEMM_SMEM>>>(
        grq, grk, grv, grw, bq, bk, bv, gq, gk, gv);

    // attention output reuses g_rq (Q projection already consumed it)
    attn_kernel<<<dim3(16, 64), dim3(128), ATTN_SMEM>>>(grq);

    gemm_o<<<dim3(8, 64), 256, GEMM_SMEM>>>(grq, grw + 3 * EE, bo, out);
}

// round 16
// speedup vs baseline: 1.0844x; 1.0759x over previous
#include <cuda_runtime.h>
#include <cstdint>

#define EMBED   1024
#define NHEADS  16
#define HDIM    64
#define BATCH   4
#define SEQ     2048
#define MROWS   (BATCH * SEQ)                   // 8192
#define HEADEL  (BATCH * NHEADS * SEQ * HDIM)   // 8388608
#define EE      (EMBED * EMBED)

// Scratch (static device globals: allocation-free rule).
__device__ float g_Q[HEADEL];
__device__ float g_K[HEADEL];
__device__ float g_V[HEADEL];
__device__ float g_rq[MROWS * EMBED];
__device__ float g_rk[MROWS * EMBED];
__device__ float g_rv[MROWS * EMBED];
__device__ float g_rw[4 * EE];

// ---------------- helpers ----------------
__device__ __forceinline__ uint32_t f2tf(float x) {
    uint32_t u;
    asm("cvt.rna.tf32.f32 %0, %1;" : "=r"(u) : "f"(x));
    return u;
}
__device__ __forceinline__ float tf32r(float x) {
    return __uint_as_float(f2tf(x));
}
__device__ __forceinline__ float ex2(float x) {
    float y;
    asm("ex2.approx.f32 %0, %1;" : "=f"(y) : "f"(x));
    return y;
}
__device__ __forceinline__ void mma8(float* d, const uint32_t* a, const uint32_t* b) {
    asm volatile(
        "mma.sync.aligned.m16n8k8.row.col.f32.tf32.tf32.f32 "
        "{%0,%1,%2,%3},{%4,%5,%6,%7},{%8,%9},{%0,%1,%2,%3};\n"
        : "+f"(d[0]), "+f"(d[1]), "+f"(d[2]), "+f"(d[3])
        : "r"(a[0]), "r"(a[1]), "r"(a[2]), "r"(a[3]), "r"(b[0]), "r"(b[1]));
}
__device__ __forceinline__ void cp16(float* s, const float* g) {
    uint32_t sa = (uint32_t)__cvta_generic_to_shared(s);
    asm volatile("cp.async.cg.shared.global [%0], [%1], 16;" :: "r"(sa), "l"(g));
}
#define CP_COMMIT() asm volatile("cp.async.commit_group;")
#define CP_WAIT0()  asm volatile("cp.async.wait_group 0;")
#define CP_WAIT1()  asm volatile("cp.async.wait_group 1;")

__device__ __forceinline__ uint32_t smem_u32(const void* p) {
    return (uint32_t)__cvta_generic_to_shared(p);
}
// ldmatrix x4 of 8x8 b32 tiles (b16 form, no trans; dtype-agnostic 16B row moves)
__device__ __forceinline__ void ldsm_x4(uint32_t* r, uint32_t addr) {
    asm volatile("ldmatrix.sync.aligned.m8n8.x4.shared.b16 {%0,%1,%2,%3}, [%4];"
                 : "=r"(r[0]), "=r"(r[1]), "=r"(r[2]), "=r"(r[3]) : "r"(addr));
}

// ---------------- single fused pre-round to tf32 (rna), 7 tensors ------------
__global__ void round_all_kernel(const float4* __restrict__ a0, float4* __restrict__ d0,
                                 const float4* __restrict__ a1, float4* __restrict__ d1,
                                 const float4* __restrict__ a2, float4* __restrict__ d2,
                                 const float4* __restrict__ w0, const float4* __restrict__ w1,
                                 const float4* __restrict__ w2, const float4* __restrict__ w3,
                                 float4* __restrict__ wdst, int n4x, int n4w)
{
    const int y = blockIdx.y;
    const float4* src;
    float4* dst;
    int n4;
    if (y < 3) {
        src = (y == 0) ? a0 : (y == 1) ? a1 : a2;
        dst = (y == 0) ? d0 : (y == 1) ? d1 : d2;
        n4  = n4x;
    } else {
        src = (y == 3) ? w0 : (y == 4) ? w1 : (y == 5) ? w2 : w3;
        dst = wdst + (size_t)(y - 3) * (EE / 4);
        n4  = n4w;
    }
    for (int i = blockIdx.x * blockDim.x + threadIdx.x; i < n4;
         i += gridDim.x * blockDim.x) {
        float4 v = src[i];
        dst[i] = make_float4(tf32r(v.x), tf32r(v.y), tf32r(v.z), tf32r(v.w));
    }
}

// ---------------- TN GEMM body: out = X @ W^T + bias (mma.sync + ldmatrix) ---
// 3-stage cp.async, K=32 chunks, 2 CTA/SM (108 KB smem) — measured-best config.
#define GEMM_BUF 9216            // floats per buffer (sA 128*36 + sB 128*36)
#define GEMM_STAGES 3
#define GEMM_SMEM (GEMM_STAGES * GEMM_BUF * 4)

template<int MODE>
__device__ __forceinline__ void gemm_body(const float* __restrict__ X,
                                          const float* __restrict__ W,
                                          const float* __restrict__ bias,
                                          float* __restrict__ out,
                                          float* smem, int bm, int bn)
{
    constexpr int K = EMBED, N = EMBED;
    const int tid  = threadIdx.x;
    const int lane = tid & 31;
    const int wid  = tid >> 5;
    const int wm   = wid & 1;
    const int wn   = wid >> 1;
    const int r    = lane >> 2;
    const int c    = lane & 3;
    const int lrow = lane & 7;
    const int grp  = lane >> 3;

    const uint32_t aoff = ((wm * 64 + (grp & 1) * 8 + lrow) * 36 + (grp >> 1) * 4) * 4;
    const uint32_t boff = ((wn * 32 + (grp >> 1) * 8 + lrow) * 36 + (grp & 1) * 4) * 4;

    float acc[4][4][4];
    #pragma unroll
    for (int mt = 0; mt < 4; ++mt)
        #pragma unroll
        for (int nt = 0; nt < 4; ++nt)
            #pragma unroll
            for (int e = 0; e < 4; ++e) acc[mt][nt][e] = 0.f;

    #pragma unroll
    for (int pre = 0; pre < 2; ++pre) {
        float* sA = smem + pre * GEMM_BUF;
        float* sB = sA + 4608;
        int kt = pre * 32;
        #pragma unroll
        for (int i = 0; i < 4; ++i) {
            int e = tid + i * 256, row = e >> 3, g = e & 7;
            cp16(sA + row * 36 + g * 4, X + (size_t)(bm + row) * K + kt + g * 4);
            cp16(sB + row * 36 + g * 4, W + (size_t)(bn + row) * K + kt + g * 4);
        }
        CP_COMMIT();
    }

    int p = 0;
    for (int ki = 0; ki < 32; ++ki) {
        if (ki == 31) { CP_WAIT0(); } else { CP_WAIT1(); }
        __syncthreads();

        const uint32_t sAa = smem_u32(smem + p * GEMM_BUF) + aoff;
        const uint32_t sBa = smem_u32(smem + p * GEMM_BUF + 4608) + boff;

        uint32_t af[4][4], bf[4][2];
        #pragma unroll
        for (int mt = 0; mt < 4; ++mt)
            ldsm_x4(af[mt], sAa + mt * (16 * 36 * 4));
        #pragma unroll
        for (int ntp = 0; ntp < 2; ++ntp) {
            uint32_t t[4];
            ldsm_x4(t, sBa + ntp * (16 * 36 * 4));
            bf[2 * ntp][0]     = t[0];
            bf[2 * ntp][1]     = t[1];
            bf[2 * ntp + 1][0] = t[2];
            bf[2 * ntp + 1][1] = t[3];
        }

        if (ki + 2 < 32) {
            int nb = (p + 2) % GEMM_STAGES;
            float* sA = smem + nb * GEMM_BUF;
            float* sB = sA + 4608;
            int kt = (ki + 2) * 32;
            #pragma unroll
            for (int i = 0; i < 4; ++i) {
                int e = tid + i * 256, row = e >> 3, g = e & 7;
                cp16(sA + row * 36 + g * 4, X + (size_t)(bm + row) * K + kt + g * 4);
                cp16(sB + row * 36 + g * 4, W + (size_t)(bn + row) * K + kt + g * 4);
            }
            CP_COMMIT();
        }

        #pragma unroll
        for (int kk = 0; kk < 4; ++kk) {
            if (kk > 0) {
                #pragma unroll
                for (int mt = 0; mt < 4; ++mt)
                    ldsm_x4(af[mt], sAa + mt * (16 * 36 * 4) + kk * 32);
                #pragma unroll
                for (int ntp = 0; ntp < 2; ++ntp) {
                    uint32_t t[4];
                    ldsm_x4(t, sBa + ntp * (16 * 36 * 4) + kk * 32);
                    bf[2 * ntp][0]     = t[0];
                    bf[2 * ntp][1]     = t[1];
                    bf[2 * ntp + 1][0] = t[2];
                    bf[2 * ntp + 1][1] = t[3];
                }
            }
            #pragma unroll
            for (int mt = 0; mt < 4; ++mt)
                #pragma unroll
                for (int nt = 0; nt < 4; ++nt)
                    mma8(acc[mt][nt], af[mt], bf[nt]);
        }
        p = (p + 1) % GEMM_STAGES;
    }

    // epilogue
    #pragma unroll
    for (int mt = 0; mt < 4; ++mt) {
        int row0 = bm + wm * 64 + mt * 16 + r;
        #pragma unroll
        for (int nt = 0; nt < 4; ++nt) {
            int col = bn + wn * 32 + nt * 8 + 2 * c;
            float b0 = __ldg(bias + col);
            float b1 = __ldg(bias + col + 1);
            if (MODE == 0) {
                float2 v0 = make_float2(acc[mt][nt][0] + b0, acc[mt][nt][1] + b1);
                float2 v1 = make_float2(acc[mt][nt][2] + b0, acc[mt][nt][3] + b1);
                *reinterpret_cast<float2*>(out + (size_t)row0 * N + col)       = v0;
                *reinterpret_cast<float2*>(out + (size_t)(row0 + 8) * N + col) = v1;
            } else {
                float2 v0 = make_float2(tf32r(acc[mt][nt][0] + b0), tf32r(acc[mt][nt][1] + b1));
                float2 v1 = make_float2(tf32r(acc[mt][nt][2] + b0), tf32r(acc[mt][nt][3] + b1));
                int bb = row0 >> 11;
                int l0 = row0 & (SEQ - 1);
                int h  = col >> 6;
                int dh = col & 63;
                size_t d0 = ((size_t)(bb * NHEADS + h) * SEQ + l0) * HDIM + dh;
                *reinterpret_cast<float2*>(out + d0)            = v0;
                *reinterpret_cast<float2*>(out + d0 + 8 * HDIM) = v1;
            }
        }
    }
}

// Fused Q/K/V projection: blockIdx.z in {0,1,2} selects the GEMM.
__global__ __launch_bounds__(256) void gemm_qkv(
    const float* __restrict__ X0, const float* __restrict__ X1,
    const float* __restrict__ X2, const float* __restrict__ Wbase,
    const float* __restrict__ b0, const float* __restrict__ b1,
    const float* __restrict__ b2,
    float* __restrict__ o0, float* __restrict__ o1, float* __restrict__ o2)
{
    extern __shared__ float smem[];
    const int z = blockIdx.z;
    const float* X  = (z == 0) ? X0 : (z == 1) ? X1 : X2;
    const float* bi = (z == 0) ? b0 : (z == 1) ? b1 : b2;
    float*       o  = (z == 0) ? o0 : (z == 1) ? o1 : o2;
    gemm_body<1>(X, Wbase + (size_t)z * EE, bi, o, smem,
                 blockIdx.y * 128, blockIdx.x * 128);
}

__global__ __launch_bounds__(256) void gemm_o(
    const float* __restrict__ X, const float* __restrict__ W,
    const float* __restrict__ bias, float* __restrict__ out)
{
    extern __shared__ float smem[];
    gemm_body<0>(X, W, bias, out, smem, blockIdx.y * 128, blockIdx.x * 128);
}

// ---------------- causal flash attention ----------------
// 128-row q tiles, 32 q-rows/warp, 2 CTAs/SM. LPT scheduling: grid (bh, qt)
// so the 64 heaviest CTAs (qt=15, 32 kv tiles each) occupy the lowest block
// IDs and start in wave 1; light tiles pack the tail.
#define ATTN_KS   68
#define ATTN_VS   72
#define ATTN_KB   (64 * ATTN_KS)             // 4352 floats
#define ATTN_BUF  (ATTN_KB + 64 * ATTN_VS)   // 8960 floats per KV buffer
#define ATTN_PS   (32 * 68)                  // P region floats per warp
#define ATTN_SMEM ((2 * ATTN_BUF + 4 * ATTN_PS) * 4)   // 106496 bytes
#define SM_C 0.18033688011112042f            // (1/sqrt(64)) * log2(e)

__global__ __launch_bounds__(128, 2) void attn_kernel(float* __restrict__ outAO)
{
    extern __shared__ float sm[];

    const int tid  = threadIdx.x;
    const int lane = tid & 31;
    const int wid  = tid >> 5;            // 4 warps, 32 q rows each
    const int r    = lane >> 2;
    const int c    = lane & 3;
    const int lrow = lane & 7;
    const int grp  = lane >> 3;
    const int qt   = 15 - (int)blockIdx.y;   // LPT: heavy q-tiles at low bids
    const int bh   = blockIdx.x;

    const size_t base = (size_t)bh * SEQ * HDIM;
    const float* Qp = g_Q + base;
    const float* Kp = g_K + base;
    const float* Vp = g_V + base;

    const uint32_t koff = (((grp >> 1) * 8 + lrow) * ATTN_KS + (grp & 1) * 4) * 4;
    float* pS = sm + 2 * ATTN_BUF + wid * ATTN_PS;
    const uint32_t pSa = smem_u32(pS) + (((grp & 1) * 8 + lrow) * 68 + (grp >> 1) * 4) * 4;

    // ---- stage Q (128 rows), read fragments ----
    #pragma unroll
    for (int i = 0; i < 16; ++i) {
        int e = tid + i * 128, row = e >> 4, g = e & 15;
        cp16(sm + row * ATTN_KS + g * 4, Qp + (size_t)(qt * 128 + row) * HDIM + g * 4);
    }
    CP_COMMIT();
    CP_WAIT0();
    __syncthreads();

    uint32_t qa[2][8][4];
    #pragma unroll
    for (int mt = 0; mt < 2; ++mt) {
        int row0 = wid * 32 + mt * 16 + r;
        #pragma unroll
        for (int kk = 0; kk < 8; ++kk) {
            qa[mt][kk][0] = __float_as_uint(sm[row0 * ATTN_KS + kk * 8 + c]);
            qa[mt][kk][1] = __float_as_uint(sm[(row0 + 8) * ATTN_KS + kk * 8 + c]);
            qa[mt][kk][2] = __float_as_uint(sm[row0 * ATTN_KS + kk * 8 + c + 4]);
            qa[mt][kk][3] = __float_as_uint(sm[(row0 + 8) * ATTN_KS + kk * 8 + c + 4]);
        }
    }
    __syncthreads();

    float o[2][8][4];
    #pragma unroll
    for (int mt = 0; mt < 2; ++mt)
        #pragma unroll
        for (int dt = 0; dt < 8; ++dt)
            #pragma unroll
            for (int e = 0; e < 4; ++e) o[mt][dt][e] = 0.f;

    float mrow[2][2], lrow2[2][2];
    #pragma unroll
    for (int mt = 0; mt < 2; ++mt) {
        mrow[mt][0] = -1e30f; mrow[mt][1] = -1e30f;
        lrow2[mt][0] = 0.f;   lrow2[mt][1] = 0.f;
    }

    const int qr[2] = { qt * 128 + wid * 32 + r, qt * 128 + wid * 32 + 16 + r };
    const int jt_end = 2 * qt + 1;

    {
        float* kb = sm;
        float* vb = sm + ATTN_KB;
        #pragma unroll
        for (int i = 0; i < 8; ++i) {
            int e = tid + i * 128, row = e >> 4, g = e & 15;
            cp16(kb + row * ATTN_KS + g * 4, Kp + (size_t)row * HDIM + g * 4);
            cp16(vb + row * ATTN_VS + g * 4, Vp + (size_t)row * HDIM + g * 4);
        }
        CP_COMMIT();
    }

    int p = 0;
    for (int jt = 0; jt <= jt_end; ++jt) {
        CP_WAIT0();
        __syncthreads();

        const float* kS = sm + p * ATTN_BUF;
        const float* vS = kS + ATTN_KB;
        const uint32_t kSa = smem_u32(kS) + koff;

        // ---- S = Q K^T : K-frags via ldmatrix x4 (nt pairs) ----
        float s[2][8][4];
        #pragma unroll
        for (int mt = 0; mt < 2; ++mt)
            #pragma unroll
            for (int nt = 0; nt < 8; ++nt)
                #pragma unroll
                for (int e = 0; e < 4; ++e) s[mt][nt][e] = 0.f;

        #pragma unroll
        for (int kk = 0; kk < 8; ++kk) {
            #pragma unroll
            for (int ntp = 0; ntp < 4; ++ntp) {
                uint32_t t[4];
                ldsm_x4(t, kSa + ntp * (16 * ATTN_KS * 4) + kk * 32);
                mma8(s[0][2 * ntp],     qa[0][kk], &t[0]);
                mma8(s[1][2 * ntp],     qa[1][kk], &t[0]);
                mma8(s[0][2 * ntp + 1], qa[0][kk], &t[2]);
                mma8(s[1][2 * ntp + 1], qa[1][kk], &t[2]);
            }
        }

        // prefetch next KV tile AFTER the S MMAs have been issued
        if (jt + 1 <= jt_end) {
            float* kb = sm + (p ^ 1) * ATTN_BUF;
            float* vb = kb + ATTN_KB;
            #pragma unroll
            for (int i = 0; i < 8; ++i) {
                int e = tid + i * 128, row = e >> 4, g = e & 15;
                cp16(kb + row * ATTN_KS + g * 4, Kp + (size_t)((jt + 1) * 64 + row) * HDIM + g * 4);
                cp16(vb + row * ATTN_VS + g * 4, Vp + (size_t)((jt + 1) * 64 + row) * HDIM + g * 4);
            }
            CP_COMMIT();
        }

        // ---- causal mask ----
        if (jt >= 2 * qt) {
            #pragma unroll
            for (int mt = 0; mt < 2; ++mt)
                #pragma unroll
                for (int nt = 0; nt < 8; ++nt) {
                    int kc = jt * 64 + nt * 8 + 2 * c;
                    if (kc > qr[mt])         s[mt][nt][0] = -1e30f;
                    if (kc + 1 > qr[mt])     s[mt][nt][1] = -1e30f;
                    if (kc > qr[mt] + 8)     s[mt][nt][2] = -1e30f;
                    if (kc + 1 > qr[mt] + 8) s[mt][nt][3] = -1e30f;
                }
        }

        // ---- online softmax (exp2 domain) ----
        #pragma unroll
        for (int mt = 0; mt < 2; ++mt) {
            float rmax0 = -1e30f, rmax1 = -1e30f;
            #pragma unroll
            for (int nt = 0; nt < 8; ++nt) {
                rmax0 = fmaxf(rmax0, fmaxf(s[mt][nt][0], s[mt][nt][1]));
                rmax1 = fmaxf(rmax1, fmaxf(s[mt][nt][2], s[mt][nt][3]));
            }
            rmax0 = fmaxf(rmax0, __shfl_xor_sync(0xFFFFFFFFu, rmax0, 1));
            rmax0 = fmaxf(rmax0, __shfl_xor_sync(0xFFFFFFFFu, rmax0, 2));
            rmax1 = fmaxf(rmax1, __shfl_xor_sync(0xFFFFFFFFu, rmax1, 1));
            rmax1 = fmaxf(rmax1, __shfl_xor_sync(0xFFFFFFFFu, rmax1, 2));

            float mn0 = fmaxf(mrow[mt][0], rmax0);
            float mn1 = fmaxf(mrow[mt][1], rmax1);
            float f0 = ex2((mrow[mt][0] - mn0) * SM_C);
            float f1 = ex2((mrow[mt][1] - mn1) * SM_C);
            float mc0 = mn0 * SM_C, mc1 = mn1 * SM_C;
            float rs0 = 0.f, rs1 = 0.f;
            #pragma unroll
            for (int nt = 0; nt < 8; ++nt) {
                s[mt][nt][0] = ex2(fmaf(s[mt][nt][0], SM_C, -mc0));
                s[mt][nt][1] = ex2(fmaf(s[mt][nt][1], SM_C, -mc0));
                s[mt][nt][2] = ex2(fmaf(s[mt][nt][2], SM_C, -mc1));
                s[mt][nt][3] = ex2(fmaf(s[mt][nt][3], SM_C, -mc1));
                rs0 += s[mt][nt][0] + s[mt][nt][1];
                rs1 += s[mt][nt][2] + s[mt][nt][3];
            }
            rs0 += __shfl_xor_sync(0xFFFFFFFFu, rs0, 1);
            rs0 += __shfl_xor_sync(0xFFFFFFFFu, rs0, 2);
            rs1 += __shfl_xor_sync(0xFFFFFFFFu, rs1, 1);
            rs1 += __shfl_xor_sync(0xFFFFFFFFu, rs1, 2);
            lrow2[mt][0] = lrow2[mt][0] * f0 + rs0;
            lrow2[mt][1] = lrow2[mt][1] * f1 + rs1;
            mrow[mt][0] = mn0; mrow[mt][1] = mn1;
            #pragma unroll
            for (int dt = 0; dt < 8; ++dt) {
                o[mt][dt][0] *= f0; o[mt][dt][1] *= f0;
                o[mt][dt][2] *= f1; o[mt][dt][3] *= f1;
            }
        }

        // ---- stage P (tf32) to per-warp smem, read back as A-frags ----
        #pragma unroll
        for (int mt = 0; mt < 2; ++mt)
            #pragma unroll
            for (int kk = 0; kk < 8; ++kk) {
                uint32_t* w0 = reinterpret_cast<uint32_t*>(
                    pS + (mt * 16 + r) * 68 + kk * 8 + 2 * c);
                w0[0] = f2tf(s[mt][kk][0]);
                w0[1] = f2tf(s[mt][kk][1]);
                uint32_t* w1 = reinterpret_cast<uint32_t*>(
                    pS + (mt * 16 + 8 + r) * 68 + kk * 8 + 2 * c);
                w1[0] = f2tf(s[mt][kk][2]);
                w1[1] = f2tf(s[mt][kk][3]);
            }
        __syncwarp();

        // ---- O += P V ----
        #pragma unroll
        for (int kk = 0; kk < 8; ++kk) {
            uint32_t pa0[4], pa1[4];
            ldsm_x4(pa0, pSa + kk * 32);
            ldsm_x4(pa1, pSa + 16 * 68 * 4 + kk * 32);
            #pragma unroll
            for (int dt = 0; dt < 8; ++dt) {
                uint32_t vb[2];
                vb[0] = __float_as_uint(vS[(kk * 8 + c) * ATTN_VS + dt * 8 + r]);
                vb[1] = __float_as_uint(vS[(kk * 8 + c + 4) * ATTN_VS + dt * 8 + r]);
                mma8(o[0][dt], pa0, vb);
                mma8(o[1][dt], pa1, vb);
            }
        }
        __syncwarp();
        p ^= 1;
    }

    // ---- epilogue ----
    int b = bh >> 4, h = bh & 15;
    #pragma unroll
    for (int mt = 0; mt < 2; ++mt) {
        float il0 = 1.f / lrow2[mt][0], il1 = 1.f / lrow2[mt][1];
        float* op  = outAO + ((size_t)(b * SEQ + qr[mt])) * EMBED + h * HDIM;
        float* op1 = op + (size_t)8 * EMBED;
        #pragma unroll
        for (int dt = 0; dt < 8; ++dt) {
            float2 v0 = make_float2(tf32r(o[mt][dt][0] * il0), tf32r(o[mt][dt][1] * il0));
            float2 v1 = make_float2(tf32r(o[mt][dt][2] * il1), tf32r(o[mt][dt][3] * il1));
            *reinterpret_cast<float2*>(op  + dt * 8 + 2 * c) = v0;
            *reinterpret_cast<float2*>(op1 + dt * 8 + 2 * c) = v1;
        }
    }
}

// ---------------- launch ----------------
extern "C" void kernel_launch(void* const* d_in, const int* in_sizes, int n_in,
                              void* d_out, int out_size)
{
    (void)in_sizes; (void)n_in; (void)out_size;
    const float* query = (const float*)d_in[0];
    const float* key   = (const float*)d_in[1];
    const float* value = (const float*)d_in[2];
    const float* Wq    = (const float*)d_in[3];
    const float* bq    = (const float*)d_in[4];
    const float* Wk    = (const float*)d_in[5];
    const float* bk    = (const float*)d_in[6];
    const float* Wv    = (const float*)d_in[7];
    const float* bv    = (const float*)d_in[8];
    const float* Wo    = (const float*)d_in[9];
    const float* bo    = (const float*)d_in[10];
    float* out = (float*)d_out;

    cudaFuncSetAttribute(gemm_qkv, cudaFuncAttributeMaxDynamicSharedMemorySize, GEMM_SMEM);
    cudaFuncSetAttribute(gemm_o,   cudaFuncAttributeMaxDynamicSharedMemorySize, GEMM_SMEM);
    cudaFuncSetAttribute(attn_kernel, cudaFuncAttributeMaxDynamicSharedMemorySize, ATTN_SMEM);

    float *gq, *gk, *gv, *grq, *grk, *grv, *grw;
    cudaGetSymbolAddress((void**)&gq,  g_Q);
    cudaGetSymbolAddress((void**)&gk,  g_K);
    cudaGetSymbolAddress((void**)&gv,  g_V);
    cudaGetSymbolAddress((void**)&grq, g_rq);
    cudaGetSymbolAddress((void**)&grk, g_rk);
    cudaGetSymbolAddress((void**)&grv, g_rv);
    cudaGetSymbolAddress((void**)&grw, g_rw);

    const int n4x = MROWS * EMBED / 4;
    const int n4w = EE / 4;

    // Single fused rounding launch (7 tensors via blockIdx.y)
    round_all_kernel<<<dim3(1024, 7), 256>>>(
        (const float4*)query, (float4*)grq,
        (const float4*)key,   (float4*)grk,
        (const float4*)value, (float4*)grv,
        (const float4*)Wq, (const float4*)Wk, (const float4*)Wv, (const float4*)Wo,
        (float4*)grw, n4x, n4w);

    // Fused Q/K/V projections in one launch
    gemm_qkv<<<dim3(8, 64, 3), 256, GEMM_SMEM>>>(
        grq, grk, grv, grw, bq, bk, bv, gq, gk, gv);

    // attention output reuses g_rq (Q projection already consumed it)
    // LPT grid: (bh, qt-index) — heaviest q-tiles get the lowest block IDs
    attn_kernel<<<dim3(64, 16), dim3(128), ATTN_SMEM>>>(grq);

    gemm_o<<<dim3(8, 64), 256, GEMM_SMEM>>>(grq, grw + 3 * EE, bo, out);
}